// round 6
// baseline (speedup 1.0000x reference)
#include <cuda_runtime.h>
#include <cstdint>

// ---------------------------------------------------------------- dims
#define T_STEPS 32
#define B_DIM   256
#define F_DIM   2048
#define H_DIM   4096
#define M_DIM   (T_STEPS * B_DIM)   // 8192
#define K_DIM   F_DIM               // 2048
#define N_DIM   H_DIM               // 4096
#define BH      (B_DIM * H_DIM)     // 1048576

// scratch for cur[T*B, H]
__device__ float g_cur[(size_t)M_DIM * N_DIM];   // 128 MB

// ---------------------------------------------------------------- GEMM
// C[M,N] = A[M,K] @ W[N,K]^T + bias[N]
// 128x128 tile, BK=16, 256 threads, 8x8 micro-tile.
// Packed fp32x2 FMA (fma.rn.f32x2): two IEEE fp32 fma.rn per instruction.
// Per-element rounding, k order, and single-accumulator semantics are
// IDENTICAL to the scalar round-5 kernel -> bit-exact output (rel_err 0.0).
#define BM  128
#define BN  128
#define BK  16
#define ASTRIDE 130   // u64 per k-row of duplicated A  (128 + pad 2)
#define BSTRIDE 132   // floats per k-row of B          (128 + pad 4)
#define AS_BYTES (2 * BK * ASTRIDE * 8)          // 33280
#define BS_BYTES (2 * BK * BSTRIDE * 4)          // 16896
#define SMEM_DYN (AS_BYTES + BS_BYTES)           // 50176

__device__ __forceinline__ void fma2(unsigned long long& d,
                                     unsigned long long a,
                                     unsigned long long b) {
    asm("fma.rn.f32x2 %0, %1, %2, %0;" : "+l"(d) : "l"(a), "l"(b));
}

__device__ __forceinline__ unsigned long long dup2(float x) {
    unsigned long long d;
    uint32_t u = __float_as_uint(x);
    asm("mov.b64 %0, {%1, %2};" : "=l"(d) : "r"(u), "r"(u));
    return d;
}

__device__ __forceinline__ void unpack2(unsigned long long v, float& lo, float& hi) {
    uint32_t l, h;
    asm("mov.b64 {%0, %1}, %2;" : "=r"(l), "=r"(h) : "l"(v));
    lo = __uint_as_float(l);
    hi = __uint_as_float(h);
}

__global__ __launch_bounds__(256, 2)
void gemm_f32x2(const float* __restrict__ A,
                const float* __restrict__ W,
                const float* __restrict__ bias)
{
    extern __shared__ char smem_raw[];
    unsigned long long* As2 = (unsigned long long*)smem_raw;   // [2][BK][ASTRIDE]
    float* Bs = (float*)(smem_raw + AS_BYTES);                 // [2][BK][BSTRIDE]

    const int tid = threadIdx.x;
    const int tx  = tid & 15;    // N direction
    const int ty  = tid >> 4;    // M direction

    const int rowBase = blockIdx.y * BM;
    const int colBase = blockIdx.x * BN;

    // loader indices
    const int r0 = tid >> 2;          // 0..63
    const int r1 = r0 + 64;           // 64..127
    const int kq = (tid & 3) << 2;    // 0,4,8,12

    const float* ApA = A + (size_t)(rowBase + r0) * K_DIM + kq;
    const float* ApB = A + (size_t)(rowBase + r1) * K_DIM + kq;
    const float* WpA = W + (size_t)(colBase + r0) * K_DIM + kq;
    const float* WpB = W + (size_t)(colBase + r1) * K_DIM + kq;

    // acc2[i][p] = (C[i][2p], C[i][2p+1]) packed fp32x2
    unsigned long long acc2[8][4];
#pragma unroll
    for (int i = 0; i < 8; i++)
#pragma unroll
        for (int p = 0; p < 4; p++) acc2[i][p] = 0ULL;

    // prologue: LDG chunk 0, STS into buf 0
    float4 av0 = *(const float4*)(ApA);
    float4 av1 = *(const float4*)(ApB);
    float4 bv0 = *(const float4*)(WpA);
    float4 bv1 = *(const float4*)(WpB);
    {
        As2[(kq + 0) * ASTRIDE + r0] = dup2(av0.x);
        As2[(kq + 1) * ASTRIDE + r0] = dup2(av0.y);
        As2[(kq + 2) * ASTRIDE + r0] = dup2(av0.z);
        As2[(kq + 3) * ASTRIDE + r0] = dup2(av0.w);
        As2[(kq + 0) * ASTRIDE + r1] = dup2(av1.x);
        As2[(kq + 1) * ASTRIDE + r1] = dup2(av1.y);
        As2[(kq + 2) * ASTRIDE + r1] = dup2(av1.z);
        As2[(kq + 3) * ASTRIDE + r1] = dup2(av1.w);
        Bs[(kq + 0) * BSTRIDE + r0] = bv0.x;
        Bs[(kq + 1) * BSTRIDE + r0] = bv0.y;
        Bs[(kq + 2) * BSTRIDE + r0] = bv0.z;
        Bs[(kq + 3) * BSTRIDE + r0] = bv0.w;
        Bs[(kq + 0) * BSTRIDE + r1] = bv1.x;
        Bs[(kq + 1) * BSTRIDE + r1] = bv1.y;
        Bs[(kq + 2) * BSTRIDE + r1] = bv1.z;
        Bs[(kq + 3) * BSTRIDE + r1] = bv1.w;
    }
    __syncthreads();

    const int NIT = K_DIM / BK;   // 128
    for (int it = 0; it < NIT; it++) {
        const int cur = it & 1;
        const int nxt = cur ^ 1;

        // issue next chunk's global loads early
        if (it + 1 < NIT) {
            const size_t off = (size_t)(it + 1) * BK;
            av0 = *(const float4*)(ApA + off);
            av1 = *(const float4*)(ApB + off);
            bv0 = *(const float4*)(WpA + off);
            bv1 = *(const float4*)(WpB + off);
        }

        // compute on current buffer; k ascending, single packed accumulator
        const unsigned long long* Ab = As2 + cur * BK * ASTRIDE;
        const float* Bb = Bs + cur * BK * BSTRIDE;
#pragma unroll
        for (int k = 0; k < BK; k++) {
            unsigned long long a8[8], bp[4];
            const unsigned long long* ar = Ab + k * ASTRIDE + ty * 8;
            ulonglong2 q0 = *(const ulonglong2*)(ar + 0);
            ulonglong2 q1 = *(const ulonglong2*)(ar + 2);
            ulonglong2 q2 = *(const ulonglong2*)(ar + 4);
            ulonglong2 q3 = *(const ulonglong2*)(ar + 6);
            a8[0] = q0.x; a8[1] = q0.y; a8[2] = q1.x; a8[3] = q1.y;
            a8[4] = q2.x; a8[5] = q2.y; a8[6] = q3.x; a8[7] = q3.y;
            const float* br = Bb + k * BSTRIDE + tx * 8;
            ulonglong2 p0 = *(const ulonglong2*)(br + 0);
            ulonglong2 p1 = *(const ulonglong2*)(br + 4);
            bp[0] = p0.x; bp[1] = p0.y; bp[2] = p1.x; bp[3] = p1.y;
#pragma unroll
            for (int i = 0; i < 8; i++)
#pragma unroll
                for (int p = 0; p < 4; p++)
                    fma2(acc2[i][p], a8[i], bp[p]);
        }

        // store next chunk into the other buffer
        if (it + 1 < NIT) {
            unsigned long long* An = As2 + nxt * BK * ASTRIDE;
            float* Bn = Bs + nxt * BK * BSTRIDE;
            An[(kq + 0) * ASTRIDE + r0] = dup2(av0.x);
            An[(kq + 1) * ASTRIDE + r0] = dup2(av0.y);
            An[(kq + 2) * ASTRIDE + r0] = dup2(av0.z);
            An[(kq + 3) * ASTRIDE + r0] = dup2(av0.w);
            An[(kq + 0) * ASTRIDE + r1] = dup2(av1.x);
            An[(kq + 1) * ASTRIDE + r1] = dup2(av1.y);
            An[(kq + 2) * ASTRIDE + r1] = dup2(av1.z);
            An[(kq + 3) * ASTRIDE + r1] = dup2(av1.w);
            Bn[(kq + 0) * BSTRIDE + r0] = bv0.x;
            Bn[(kq + 1) * BSTRIDE + r0] = bv0.y;
            Bn[(kq + 2) * BSTRIDE + r0] = bv0.z;
            Bn[(kq + 3) * BSTRIDE + r0] = bv0.w;
            Bn[(kq + 0) * BSTRIDE + r1] = bv1.x;
            Bn[(kq + 1) * BSTRIDE + r1] = bv1.y;
            Bn[(kq + 2) * BSTRIDE + r1] = bv1.z;
            Bn[(kq + 3) * BSTRIDE + r1] = bv1.w;
        }
        __syncthreads();
    }

    // epilogue: unpack, add bias (single fp32 add as before), store
#pragma unroll
    for (int i = 0; i < 8; i++) {
        int row = rowBase + ty * 8 + i;
        float* Cp = g_cur + (size_t)row * N_DIM + colBase + tx * 8;
#pragma unroll
        for (int h = 0; h < 2; h++) {
            int col = colBase + tx * 8 + h * 4;
            float c0, c1, c2, c3;
            unpack2(acc2[i][h * 2 + 0], c0, c1);
            unpack2(acc2[i][h * 2 + 1], c2, c3);
            float4 v;
            v.x = c0 + bias[col + 0];
            v.y = c1 + bias[col + 1];
            v.z = c2 + bias[col + 2];
            v.w = c3 + bias[col + 3];
            *(float4*)(Cp + h * 4) = v;
        }
    }
}

// ---------------------------------------------------------------- LIF scan
__global__ __launch_bounds__(256)
void lif_kernel(float* __restrict__ out)
{
    int i4 = blockIdx.x * blockDim.x + threadIdx.x;
    if (i4 >= BH / 4) return;

    const float4* cur4 = (const float4*)g_cur;
    float4* out4 = (float4*)out;

    float v0 = 0.f, v1 = 0.f, v2 = 0.f, v3 = 0.f;
    float c0 = 0.f, c1 = 0.f, c2 = 0.f, c3 = 0.f;
#pragma unroll
    for (int t = 0; t < T_STEPS; t++) {
        float4 x = cur4[(size_t)t * (BH / 4) + i4];
        float4 s;
        v0 = __fadd_rn(v0, __fmul_rn(__fsub_rn(x.x, v0), 0.5f));
        v1 = __fadd_rn(v1, __fmul_rn(__fsub_rn(x.y, v1), 0.5f));
        v2 = __fadd_rn(v2, __fmul_rn(__fsub_rn(x.z, v2), 0.5f));
        v3 = __fadd_rn(v3, __fmul_rn(__fsub_rn(x.w, v3), 0.5f));
        bool f0 = v0 >= 1.0f, f1 = v1 >= 1.0f, f2 = v2 >= 1.0f, f3 = v3 >= 1.0f;
        s.x = f0 ? 1.f : 0.f; s.y = f1 ? 1.f : 0.f;
        s.z = f2 ? 1.f : 0.f; s.w = f3 ? 1.f : 0.f;
        out4[(size_t)t * (BH / 4) + i4] = s;
        c0 += s.x; c1 += s.y; c2 += s.z; c3 += s.w;
        v0 = f0 ? 0.f : v0; v1 = f1 ? 0.f : v1;
        v2 = f2 ? 0.f : v2; v3 = f3 ? 0.f : v3;
    }
    out4[(size_t)T_STEPS * (BH / 4) + i4] = make_float4(c0, c1, c2, c3);
}

// ---------------------------------------------------------------- launch
extern "C" void kernel_launch(void* const* d_in, const int* in_sizes, int n_in,
                              void* d_out, int out_size)
{
    const float* x_seq = (const float*)d_in[0];  // [T,B,F]
    const float* W     = (const float*)d_in[1];  // [H,F]
    const float* b     = (const float*)d_in[2];  // [H]
    float* out = (float*)d_out;

    cudaFuncSetAttribute(gemm_f32x2,
                         cudaFuncAttributeMaxDynamicSharedMemorySize, SMEM_DYN);

    dim3 gg(N_DIM / BN, M_DIM / BM);   // (32, 64)
    gemm_f32x2<<<gg, 256, SMEM_DYN>>>(x_seq, W, b);

    lif_kernel<<<(BH / 4 + 255) / 256, 256>>>(out);
}

// round 7
// speedup vs baseline: 1.2011x; 1.2011x over previous
#include <cuda_runtime.h>
#include <cstdint>

// ---------------------------------------------------------------- dims
#define T_STEPS 32
#define B_DIM   256
#define F_DIM   2048
#define H_DIM   4096
#define M_DIM   (T_STEPS * B_DIM)   // 8192
#define K_DIM   F_DIM               // 2048
#define N_DIM   H_DIM               // 4096
#define BH      (B_DIM * H_DIM)     // 1048576

// scratch for cur[T*B, H]
__device__ float g_cur[(size_t)M_DIM * N_DIM];   // 128 MB

// ---------------------------------------------------------------- GEMM
// C[M,N] = A[M,K] @ W[N,K]^T + bias[N]
// Same tiling/smem layout/traffic as the round-5 kernel (128x128, BK=16,
// 256 thr, 8x8 micro-tile, reg-staged double buffer). Only change: the
// 64 scalar FFMAs per k become 32 packed fma.rn.f32x2, with A duplicated
// into (a,a) pairs in REGISTERS (mov.b64) so smem layout is untouched.
// Per-element rounding/order identical -> bit-exact (rel_err 0.0).
#define BM  128
#define BN  128
#define BK  16
#define PAD 4

__device__ __forceinline__ void fma2(unsigned long long& d,
                                     unsigned long long a,
                                     unsigned long long b) {
    asm("fma.rn.f32x2 %0, %1, %2, %0;" : "+l"(d) : "l"(a), "l"(b));
}

__device__ __forceinline__ unsigned long long dup2(float x) {
    unsigned long long d;
    uint32_t u = __float_as_uint(x);
    asm("mov.b64 %0, {%1, %2};" : "=l"(d) : "r"(u), "r"(u));
    return d;
}

__device__ __forceinline__ void unpack2(unsigned long long v, float& lo, float& hi) {
    uint32_t l, h;
    asm("mov.b64 {%0, %1}, %2;" : "=r"(l), "=r"(h) : "l"(v));
    lo = __uint_as_float(l);
    hi = __uint_as_float(h);
}

__global__ __launch_bounds__(256, 2)
void gemm_f32x2_regdup(const float* __restrict__ A,
                       const float* __restrict__ W,
                       const float* __restrict__ bias)
{
    __shared__ __align__(16) float As[2][BK][BM + PAD];
    __shared__ __align__(16) float Bs[2][BK][BM + PAD];

    const int tid = threadIdx.x;
    const int tx  = tid & 15;    // N direction
    const int ty  = tid >> 4;    // M direction

    const int rowBase = blockIdx.y * BM;
    const int colBase = blockIdx.x * BN;

    // loader indices
    const int r0 = tid >> 2;          // 0..63
    const int r1 = r0 + 64;           // 64..127
    const int kq = (tid & 3) << 2;    // 0,4,8,12

    const float* ApA = A + (size_t)(rowBase + r0) * K_DIM + kq;
    const float* ApB = A + (size_t)(rowBase + r1) * K_DIM + kq;
    const float* WpA = W + (size_t)(colBase + r0) * K_DIM + kq;
    const float* WpB = W + (size_t)(colBase + r1) * K_DIM + kq;

    // acc2[i][p] = (C[i][2p], C[i][2p+1]) packed fp32x2
    unsigned long long acc2[8][4];
#pragma unroll
    for (int i = 0; i < 8; i++)
#pragma unroll
        for (int p = 0; p < 4; p++) acc2[i][p] = 0ULL;

    // prologue: LDG chunk 0, STS into buf 0
    float4 av0 = *(const float4*)(ApA);
    float4 av1 = *(const float4*)(ApB);
    float4 bv0 = *(const float4*)(WpA);
    float4 bv1 = *(const float4*)(WpB);
    {
        As[0][kq + 0][r0] = av0.x; As[0][kq + 1][r0] = av0.y;
        As[0][kq + 2][r0] = av0.z; As[0][kq + 3][r0] = av0.w;
        As[0][kq + 0][r1] = av1.x; As[0][kq + 1][r1] = av1.y;
        As[0][kq + 2][r1] = av1.z; As[0][kq + 3][r1] = av1.w;
        Bs[0][kq + 0][r0] = bv0.x; Bs[0][kq + 1][r0] = bv0.y;
        Bs[0][kq + 2][r0] = bv0.z; Bs[0][kq + 3][r0] = bv0.w;
        Bs[0][kq + 0][r1] = bv1.x; Bs[0][kq + 1][r1] = bv1.y;
        Bs[0][kq + 2][r1] = bv1.z; Bs[0][kq + 3][r1] = bv1.w;
    }
    __syncthreads();

    const int NIT = K_DIM / BK;   // 128
    for (int it = 0; it < NIT; it++) {
        const int cur = it & 1;
        const int nxt = cur ^ 1;

        // issue next chunk's global loads early (latency hidden by compute)
        if (it + 1 < NIT) {
            const size_t off = (size_t)(it + 1) * BK;
            av0 = *(const float4*)(ApA + off);
            av1 = *(const float4*)(ApB + off);
            bv0 = *(const float4*)(WpA + off);
            bv1 = *(const float4*)(WpB + off);
        }

        // compute on current buffer; k ascending, single packed accumulator
#pragma unroll
        for (int k = 0; k < BK; k++) {
            float4 t0 = *(const float4*)&As[cur][k][ty * 8];
            float4 t1 = *(const float4*)&As[cur][k][ty * 8 + 4];
            unsigned long long a2[8];
            a2[0] = dup2(t0.x); a2[1] = dup2(t0.y);
            a2[2] = dup2(t0.z); a2[3] = dup2(t0.w);
            a2[4] = dup2(t1.x); a2[5] = dup2(t1.y);
            a2[6] = dup2(t1.z); a2[7] = dup2(t1.w);

            ulonglong2 p0 = *(const ulonglong2*)&Bs[cur][k][tx * 8];
            ulonglong2 p1 = *(const ulonglong2*)&Bs[cur][k][tx * 8 + 4];
            unsigned long long bp[4];
            bp[0] = p0.x; bp[1] = p0.y; bp[2] = p1.x; bp[3] = p1.y;

#pragma unroll
            for (int i = 0; i < 8; i++)
#pragma unroll
                for (int p = 0; p < 4; p++)
                    fma2(acc2[i][p], a2[i], bp[p]);
        }

        // store next chunk into the other buffer
        if (it + 1 < NIT) {
            As[nxt][kq + 0][r0] = av0.x; As[nxt][kq + 1][r0] = av0.y;
            As[nxt][kq + 2][r0] = av0.z; As[nxt][kq + 3][r0] = av0.w;
            As[nxt][kq + 0][r1] = av1.x; As[nxt][kq + 1][r1] = av1.y;
            As[nxt][kq + 2][r1] = av1.z; As[nxt][kq + 3][r1] = av1.w;
            Bs[nxt][kq + 0][r0] = bv0.x; Bs[nxt][kq + 1][r0] = bv0.y;
            Bs[nxt][kq + 2][r0] = bv0.z; Bs[nxt][kq + 3][r0] = bv0.w;
            Bs[nxt][kq + 0][r1] = bv1.x; Bs[nxt][kq + 1][r1] = bv1.y;
            Bs[nxt][kq + 2][r1] = bv1.z; Bs[nxt][kq + 3][r1] = bv1.w;
        }
        __syncthreads();
    }

    // epilogue: unpack, add bias (single fp32 add as before), store
#pragma unroll
    for (int i = 0; i < 8; i++) {
        int row = rowBase + ty * 8 + i;
        float* Cp = g_cur + (size_t)row * N_DIM + colBase + tx * 8;
#pragma unroll
        for (int h = 0; h < 2; h++) {
            int col = colBase + tx * 8 + h * 4;
            float c0, c1, c2, c3;
            unpack2(acc2[i][h * 2 + 0], c0, c1);
            unpack2(acc2[i][h * 2 + 1], c2, c3);
            float4 v;
            v.x = c0 + bias[col + 0];
            v.y = c1 + bias[col + 1];
            v.z = c2 + bias[col + 2];
            v.w = c3 + bias[col + 3];
            *(float4*)(Cp + h * 4) = v;
        }
    }
}

// ---------------------------------------------------------------- LIF scan
__global__ __launch_bounds__(256)
void lif_kernel(float* __restrict__ out)
{
    int i4 = blockIdx.x * blockDim.x + threadIdx.x;
    if (i4 >= BH / 4) return;

    const float4* cur4 = (const float4*)g_cur;
    float4* out4 = (float4*)out;

    float v0 = 0.f, v1 = 0.f, v2 = 0.f, v3 = 0.f;
    float c0 = 0.f, c1 = 0.f, c2 = 0.f, c3 = 0.f;
#pragma unroll
    for (int t = 0; t < T_STEPS; t++) {
        float4 x = cur4[(size_t)t * (BH / 4) + i4];
        float4 s;
        v0 = __fadd_rn(v0, __fmul_rn(__fsub_rn(x.x, v0), 0.5f));
        v1 = __fadd_rn(v1, __fmul_rn(__fsub_rn(x.y, v1), 0.5f));
        v2 = __fadd_rn(v2, __fmul_rn(__fsub_rn(x.z, v2), 0.5f));
        v3 = __fadd_rn(v3, __fmul_rn(__fsub_rn(x.w, v3), 0.5f));
        bool f0 = v0 >= 1.0f, f1 = v1 >= 1.0f, f2 = v2 >= 1.0f, f3 = v3 >= 1.0f;
        s.x = f0 ? 1.f : 0.f; s.y = f1 ? 1.f : 0.f;
        s.z = f2 ? 1.f : 0.f; s.w = f3 ? 1.f : 0.f;
        out4[(size_t)t * (BH / 4) + i4] = s;
        c0 += s.x; c1 += s.y; c2 += s.z; c3 += s.w;
        v0 = f0 ? 0.f : v0; v1 = f1 ? 0.f : v1;
        v2 = f2 ? 0.f : v2; v3 = f3 ? 0.f : v3;
    }
    out4[(size_t)T_STEPS * (BH / 4) + i4] = make_float4(c0, c1, c2, c3);
}

// ---------------------------------------------------------------- launch
extern "C" void kernel_launch(void* const* d_in, const int* in_sizes, int n_in,
                              void* d_out, int out_size)
{
    const float* x_seq = (const float*)d_in[0];  // [T,B,F]
    const float* W     = (const float*)d_in[1];  // [H,F]
    const float* b     = (const float*)d_in[2];  // [H]
    float* out = (float*)d_out;

    dim3 gg(N_DIM / BN, M_DIM / BM);   // (32, 64)
    gemm_f32x2_regdup<<<gg, 256>>>(x_seq, W, b);

    lif_kernel<<<(BH / 4 + 255) / 256, 256>>>(out);
}